// round 11
// baseline (speedup 1.0000x reference)
#include <cuda_runtime.h>

// PhotonicMesh: 512-port Clements mesh, 512 layers, 1024 batch rows.
// R11 = R10 (cp.async smem coefficient ring; regs 73, no spills) with:
//  (a) cp.async.CA instead of .CG: keep L1 allocation so the ~7 co-resident
//      CTAs per SM share coefficient lines in L1 (R10's .cg bypassed L1 and
//      pushed ALL 2.2 GB of table re-reads to L2 -> L2=51.5%, the limiter).
//  (b) 3-buffer ring with wait_group 2 (prefetch 6 layers ahead) to cover
//      L2-miss latency for the lead CTA on each SM.
// Skeleton unchanged: 1024 single-warp CTAs, lane owns 16 ports, even layers
// lane-local, odd layers 4 shuffles + guarded cross pair, no barriers.

#define N_PORT  512
#define N_LAYER 512
#define N_PAIR  256
#define ATTEN_F 0.97723722095581054f   // sqrt(10^(-0.2/10))

// Coefficient table, layout: [(l*8 + k)*32 + lane] = [l*256 + k*32 + lane],
// pair p = 8*lane + k. A 2-layer block (l even) is 512 contiguous float4.
__device__ float4 g_coef[N_LAYER * N_PAIR];

__global__ void pm_coef_kernel(const float* __restrict__ thetas,
                               const float* __restrict__ phis,
                               const int*   __restrict__ mzi_idx) {
    int l = blockIdx.x;      // layer
    int p = threadIdx.x;     // pair index within layer
    float4 c = make_float4(1.0f, 0.0f, 1.0f, 0.0f);  // identity (unused slots)
    bool odd = (l & 1) != 0;
    bool valid = (!odd) || (p < N_PAIR - 1);         // odd layers have 255 pairs
    if (valid) {
        int i = odd ? (2 * p + 1) : (2 * p);         // upper port of the pair
        int m = mzi_idx[l * N_PORT + i];
        float st, ct, sp, cp;
        sincosf(thetas[m], &st, &ct);
        sincosf(phis[m],   &sp, &cp);
        c = make_float4(ct * ATTEN_F, st * ATTEN_F, cp, sp);
    }
    g_coef[(l * 8 + (p & 7)) * 32 + (p >> 3)] = c;
}

// new_i = e^{i phi}(ct*x_i + st*x_j) ; new_j = ct*x_j - st*x_i
__device__ __forceinline__ void butterfly(float2& xi, float2& xj, float4 c) {
    float ct = c.x, st = c.y, er = c.z, ei = c.w;
    float ur = ct * xi.x + st * xj.x;
    float ui = ct * xi.y + st * xj.y;
    float vr = ct * xj.x - st * xi.x;
    float vi = ct * xj.y - st * xi.y;
    xi.x = er * ur - ei * ui;
    xi.y = er * ui + ei * ur;
    xj.x = vr;
    xj.y = vi;
}

// L1-allocating async copy (keeps cross-CTA reuse in L1, unlike .cg)
__device__ __forceinline__ void cp_async16(unsigned dst_smem, const void* src) {
    asm volatile("cp.async.ca.shared.global [%0], [%1], 16;"
                 :: "r"(dst_smem), "l"(src));
}

__global__ __launch_bounds__(32)
void pm_mesh_kernel(const float* __restrict__ x, float* __restrict__ out) {
    // 3-buffer coefficient ring: [buf][slot k=0..16][lane]
    __shared__ float4 sc[3][17 * 32];

    const int lane = threadIdx.x & 31;
    const int row  = blockIdx.x;          // one warp-CTA per batch row

    float2 s[16];             // complex state: lane owns ports 16*lane..16*lane+15

    // ---- load input (real), imag = 0 ----
    const float4* x4 = reinterpret_cast<const float4*>(x);
    #pragma unroll
    for (int v = 0; v < 4; v++) {
        float4 q = x4[(size_t)row * (N_PORT / 4) + lane * 4 + v];
        s[4 * v + 0] = make_float2(q.x, 0.f);
        s[4 * v + 1] = make_float2(q.y, 0.f);
        s[4 * v + 2] = make_float2(q.z, 0.f);
        s[4 * v + 3] = make_float2(q.w, 0.f);
    }

    const int lm = (lane > 0) ? (lane - 1) : 0;   // lane0 value unused (guard)

    // stage coefficients for 2-layer block starting at even layer l into buf
    auto stage = [&](int buf, int l) {
        unsigned d0 = (unsigned)__cvta_generic_to_shared(&sc[buf][lane]);
        const float4* g = g_coef + (size_t)l * 256 + lane;
        #pragma unroll
        for (int k = 0; k < 16; k++)
            cp_async16(d0 + (unsigned)(k * 32 * 16), g + k * 32);
        // private copy of lane-1's cross coef (odd layer, pair slot k=7)
        cp_async16((unsigned)__cvta_generic_to_shared(&sc[buf][16 * 32 + lane]),
                   g_coef + (size_t)(l + 1) * 256 + 7 * 32 + lm);
        asm volatile("cp.async.commit_group;" ::: "memory");
    };

    stage(0, 0);
    stage(1, 2);
    stage(2, 4);

    int buf = 0;
    #pragma unroll 1
    for (int l = 0; l < N_LAYER; l += 2) {
        asm volatile("cp.async.wait_group 2;" ::: "memory");

        float4 c[8];

        // ---- EVEN layer l: pairs (16*lane+2k, +2k+1), lane-local ----
        #pragma unroll
        for (int k = 0; k < 8; k++) c[k] = sc[buf][k * 32 + lane];
        #pragma unroll
        for (int k = 0; k < 8; k++)
            butterfly(s[2 * k], s[2 * k + 1], c[k]);

        // ---- ODD layer l+1 ----
        #pragma unroll
        for (int k = 0; k < 8; k++) c[k] = sc[buf][(8 + k) * 32 + lane];
        float4 cx = sc[buf][16 * 32 + lane];

        // snapshot neighbor values BEFORE any update this layer
        float xjr = __shfl_down_sync(0xffffffffu, s[0].x, 1);   // (lane+1).port0
        float xji = __shfl_down_sync(0xffffffffu, s[0].y, 1);
        float xir = __shfl_up_sync(0xffffffffu, s[15].x, 1);    // (lane-1).port15
        float xii = __shfl_up_sync(0xffffffffu, s[15].y, 1);
        #pragma unroll
        for (int k = 0; k < 7; k++)
            butterfly(s[2 * k + 1], s[2 * k + 2], c[k]);
        if (lane < 31) {  // upper port of cross pair: gets the phase
            float ct = c[7].x, st = c[7].y, er = c[7].z, ei = c[7].w;
            float ur = ct * s[15].x + st * xjr;
            float ui = ct * s[15].y + st * xji;
            s[15].x = er * ur - ei * ui;
            s[15].y = er * ui + ei * ur;
        }
        if (lane > 0) {   // lower port of cross pair: real coefficients
            float2 x0 = s[0];
            s[0].x = cx.x * x0.x - cx.y * xir;
            s[0].y = cx.x * x0.y - cx.y * xii;
        }

        // refill this buffer for layers l+6 (clamped; tail data never used)
        int ln = l + 6;  if (ln > N_LAYER - 2) ln = 0;
        stage(buf, ln);

        buf = (buf == 2) ? 0 : (buf + 1);
    }

    // ---- square-law detection + store ----
    float4* o4 = reinterpret_cast<float4*>(out);
    #pragma unroll
    for (int v = 0; v < 4; v++) {
        float4 q;
        q.x = s[4 * v + 0].x * s[4 * v + 0].x + s[4 * v + 0].y * s[4 * v + 0].y;
        q.y = s[4 * v + 1].x * s[4 * v + 1].x + s[4 * v + 1].y * s[4 * v + 1].y;
        q.z = s[4 * v + 2].x * s[4 * v + 2].x + s[4 * v + 2].y * s[4 * v + 2].y;
        q.w = s[4 * v + 3].x * s[4 * v + 3].x + s[4 * v + 3].y * s[4 * v + 3].y;
        o4[(size_t)row * (N_PORT / 4) + lane * 4 + v] = q;
    }
}

extern "C" void kernel_launch(void* const* d_in, const int* in_sizes, int n_in,
                              void* d_out, int out_size) {
    const float* x       = (const float*)d_in[0];
    const float* thetas  = (const float*)d_in[1];
    const float* phis    = (const float*)d_in[2];
    // d_in[3] = partner (unused: structure is static)
    const int*   mzi_idx = (const int*)d_in[4];
    // d_in[5] = role (unused: structure is static)
    float* out = (float*)d_out;

    pm_coef_kernel<<<N_LAYER, N_PAIR>>>(thetas, phis, mzi_idx);
    // 1024 single-warp CTAs: spread across ALL SMs (~7 per SM on 148+ SMs)
    pm_mesh_kernel<<<1024, 32>>>(x, out);
}

// round 12
// speedup vs baseline: 1.3380x; 1.3380x over previous
#include <cuda_runtime.h>

// PhotonicMesh: 512-port Clements mesh, 512 layers, 1024 batch rows.
// R12 = R10 (cp.async.cg smem coefficient ring, 1024 single-warp CTAs,
// lane owns 16 ports, no barriers; regs 73, no spills) with:
//  (a) 3-buffer ring + wait_group 2: ~3 iterations of prefetch slack so the
//      L2 latency of the lead CTA never reaches the wait (R10's 2-buffer /
//      wait 1 exposed it; R11 proved .ca is worse: L1 82% wall -> keep .cg).
//  (b) 16 slots instead of 17: the cross-pair coefficient is recovered by
//      __shfl_up of the loaded c[7] (coefs are immutable; no hazard).
//  (c) consume-then-refill: after the wait, LDS all 16 coefs to registers,
//      immediately refill the buffer (cp.async in flight under the whole
//      2-layer FFMA block), then compute.

#define N_PORT  512
#define N_LAYER 512
#define N_PAIR  256
#define ATTEN_F 0.97723722095581054f   // sqrt(10^(-0.2/10))

// Coefficient table, layout: [(l*8 + k)*32 + lane] = [l*256 + k*32 + lane],
// pair p = 8*lane + k. A 2-layer block (l even) is 512 contiguous float4.
__device__ float4 g_coef[N_LAYER * N_PAIR];

__global__ void pm_coef_kernel(const float* __restrict__ thetas,
                               const float* __restrict__ phis,
                               const int*   __restrict__ mzi_idx) {
    int l = blockIdx.x;      // layer
    int p = threadIdx.x;     // pair index within layer
    float4 c = make_float4(1.0f, 0.0f, 1.0f, 0.0f);  // identity (unused slots)
    bool odd = (l & 1) != 0;
    bool valid = (!odd) || (p < N_PAIR - 1);         // odd layers have 255 pairs
    if (valid) {
        int i = odd ? (2 * p + 1) : (2 * p);         // upper port of the pair
        int m = mzi_idx[l * N_PORT + i];
        float st, ct, sp, cp;
        sincosf(thetas[m], &st, &ct);
        sincosf(phis[m],   &sp, &cp);
        c = make_float4(ct * ATTEN_F, st * ATTEN_F, cp, sp);
    }
    g_coef[(l * 8 + (p & 7)) * 32 + (p >> 3)] = c;
}

// new_i = e^{i phi}(ct*x_i + st*x_j) ; new_j = ct*x_j - st*x_i
__device__ __forceinline__ void butterfly(float2& xi, float2& xj, float4 c) {
    float ct = c.x, st = c.y, er = c.z, ei = c.w;
    float ur = ct * xi.x + st * xj.x;
    float ui = ct * xi.y + st * xj.y;
    float vr = ct * xj.x - st * xi.x;
    float vi = ct * xj.y - st * xi.y;
    xi.x = er * ur - ei * ui;
    xi.y = er * ui + ei * ur;
    xj.x = vr;
    xj.y = vi;
}

// L2-only async copy (L1 bypass: co-resident CTAs must not thrash L1 - R11)
__device__ __forceinline__ void cp_async16(unsigned dst_smem, const void* src) {
    asm volatile("cp.async.cg.shared.global [%0], [%1], 16;"
                 :: "r"(dst_smem), "l"(src));
}

__global__ __launch_bounds__(32)
void pm_mesh_kernel(const float* __restrict__ x, float* __restrict__ out) {
    // 3-buffer coefficient ring: [buf][slot k=0..15][lane]
    __shared__ float4 sc[3][16 * 32];

    const int lane = threadIdx.x & 31;
    const int row  = blockIdx.x;          // one warp-CTA per batch row

    float2 s[16];             // complex state: lane owns ports 16*lane..16*lane+15

    // ---- load input (real), imag = 0 ----
    const float4* x4 = reinterpret_cast<const float4*>(x);
    #pragma unroll
    for (int v = 0; v < 4; v++) {
        float4 q = x4[(size_t)row * (N_PORT / 4) + lane * 4 + v];
        s[4 * v + 0] = make_float2(q.x, 0.f);
        s[4 * v + 1] = make_float2(q.y, 0.f);
        s[4 * v + 2] = make_float2(q.z, 0.f);
        s[4 * v + 3] = make_float2(q.w, 0.f);
    }

    // stage coefficients for 2-layer block starting at even layer l into buf
    auto stage = [&](int buf, int l) {
        unsigned d0 = (unsigned)__cvta_generic_to_shared(&sc[buf][lane]);
        const float4* g = g_coef + (size_t)l * 256 + lane;
        #pragma unroll
        for (int k = 0; k < 16; k++)
            cp_async16(d0 + (unsigned)(k * 32 * 16), g + k * 32);
        asm volatile("cp.async.commit_group;" ::: "memory");
    };

    stage(0, 0);
    stage(1, 2);
    stage(2, 4);

    int buf = 0;
    #pragma unroll 1
    for (int l = 0; l < N_LAYER; l += 2) {
        asm volatile("cp.async.wait_group 2;" ::: "memory");

        // ---- drain the whole buffer into registers ----
        float4 ce[8], co[8];
        #pragma unroll
        for (int k = 0; k < 8; k++) ce[k] = sc[buf][k * 32 + lane];
        #pragma unroll
        for (int k = 0; k < 8; k++) co[k] = sc[buf][(8 + k) * 32 + lane];

        // ---- immediately refill this buffer for layers l+6 ----
        int ln = l + 6;  if (ln > N_LAYER - 2) ln = 0;   // clamp (tail unused)
        stage(buf, ln);
        buf = (buf == 2) ? 0 : (buf + 1);

        // cross coef (lane-1's pair 7 of odd layer) via shuffle, not memory
        float ctp = __shfl_up_sync(0xffffffffu, co[7].x, 1);
        float stp = __shfl_up_sync(0xffffffffu, co[7].y, 1);

        // ---- EVEN layer l: pairs (16*lane+2k, +2k+1), lane-local ----
        #pragma unroll
        for (int k = 0; k < 8; k++)
            butterfly(s[2 * k], s[2 * k + 1], ce[k]);

        // ---- ODD layer l+1 ----
        // snapshot neighbor values BEFORE any update this layer
        float xjr = __shfl_down_sync(0xffffffffu, s[0].x, 1);   // (lane+1).port0
        float xji = __shfl_down_sync(0xffffffffu, s[0].y, 1);
        float xir = __shfl_up_sync(0xffffffffu, s[15].x, 1);    // (lane-1).port15
        float xii = __shfl_up_sync(0xffffffffu, s[15].y, 1);
        #pragma unroll
        for (int k = 0; k < 7; k++)
            butterfly(s[2 * k + 1], s[2 * k + 2], co[k]);
        if (lane < 31) {  // upper port of cross pair: gets the phase
            float ct = co[7].x, st = co[7].y, er = co[7].z, ei = co[7].w;
            float ur = ct * s[15].x + st * xjr;
            float ui = ct * s[15].y + st * xji;
            s[15].x = er * ur - ei * ui;
            s[15].y = er * ui + ei * ur;
        }
        if (lane > 0) {   // lower port of cross pair: real coefficients
            float2 x0 = s[0];
            s[0].x = ctp * x0.x - stp * xir;
            s[0].y = ctp * x0.y - stp * xii;
        }
    }

    // ---- square-law detection + store ----
    float4* o4 = reinterpret_cast<float4*>(out);
    #pragma unroll
    for (int v = 0; v < 4; v++) {
        float4 q;
        q.x = s[4 * v + 0].x * s[4 * v + 0].x + s[4 * v + 0].y * s[4 * v + 0].y;
        q.y = s[4 * v + 1].x * s[4 * v + 1].x + s[4 * v + 1].y * s[4 * v + 1].y;
        q.z = s[4 * v + 2].x * s[4 * v + 2].x + s[4 * v + 2].y * s[4 * v + 2].y;
        q.w = s[4 * v + 3].x * s[4 * v + 3].x + s[4 * v + 3].y * s[4 * v + 3].y;
        o4[(size_t)row * (N_PORT / 4) + lane * 4 + v] = q;
    }
}

extern "C" void kernel_launch(void* const* d_in, const int* in_sizes, int n_in,
                              void* d_out, int out_size) {
    const float* x       = (const float*)d_in[0];
    const float* thetas  = (const float*)d_in[1];
    const float* phis    = (const float*)d_in[2];
    // d_in[3] = partner (unused: structure is static)
    const int*   mzi_idx = (const int*)d_in[4];
    // d_in[5] = role (unused: structure is static)
    float* out = (float*)d_out;

    pm_coef_kernel<<<N_LAYER, N_PAIR>>>(thetas, phis, mzi_idx);
    // 1024 single-warp CTAs: spread across ALL SMs (~7 per SM on 148+ SMs)
    pm_mesh_kernel<<<1024, 32>>>(x, out);
}

// round 13
// speedup vs baseline: 1.4849x; 1.1098x over previous
#include <cuda_runtime.h>

// PhotonicMesh: 512-port Clements mesh, 512 layers, 1024 batch rows.
// R13 = R7 verbatim (best, 118.8us: 1024 single-warp CTAs, lane owns 16
// ports, register ping-pong coefficient prefetch via LDG) with ONE change:
//   __launch_bounds__(32, 1) so ptxas may use up to 255 regs/thread.
//   R7's live set is ~185 regs (32 state + 2x17 float4 coef buffers) but
//   bare __launch_bounds__(32) capped allocation at 132 -> local-memory
//   spills (the L1 traffic seen in R7/R9 profiles) on the critical path.
// Cross coef stored as float2 (saves 4 live regs); clamps via min().

#define N_PORT  512
#define N_LAYER 512
#define N_PAIR  256
#define ATTEN_F 0.97723722095581054f   // sqrt(10^(-0.2/10))

// Coefficient table, layout: [(l*8 + k)*32 + lane] where pair p = 8*lane + k.
// Per-k load across a warp is a fully coalesced 512B read.
__device__ float4 g_coef[N_LAYER * N_PAIR];

__global__ void pm_coef_kernel(const float* __restrict__ thetas,
                               const float* __restrict__ phis,
                               const int*   __restrict__ mzi_idx) {
    int l = blockIdx.x;      // layer
    int p = threadIdx.x;     // pair index within layer
    float4 c = make_float4(1.0f, 0.0f, 1.0f, 0.0f);  // identity (unused slots)
    bool odd = (l & 1) != 0;
    bool valid = (!odd) || (p < N_PAIR - 1);         // odd layers have 255 pairs
    if (valid) {
        int i = odd ? (2 * p + 1) : (2 * p);         // upper port of the pair
        int m = mzi_idx[l * N_PORT + i];
        float st, ct, sp, cp;
        sincosf(thetas[m], &st, &ct);
        sincosf(phis[m],   &sp, &cp);
        c = make_float4(ct * ATTEN_F, st * ATTEN_F, cp, sp);
    }
    g_coef[(l * 8 + (p & 7)) * 32 + (p >> 3)] = c;
}

// new_i = e^{i phi}(ct*x_i + st*x_j) ; new_j = ct*x_j - st*x_i
__device__ __forceinline__ void butterfly(float2& xi, float2& xj, float4 c) {
    float ct = c.x, st = c.y, er = c.z, ei = c.w;
    float ur = ct * xi.x + st * xj.x;
    float ui = ct * xi.y + st * xj.y;
    float vr = ct * xj.x - st * xi.x;
    float vi = ct * xj.y - st * xi.y;
    xi.x = er * ur - ei * ui;
    xi.y = er * ui + ei * ur;
    xj.x = vr;
    xj.y = vi;
}

struct CoefBlk {
    float4 c[16];   // [0..7] even-layer pairs, [8..15] odd-layer pairs
    float2 cx;      // lane-1's odd cross-pair (ct, st)
};

// Load coefficients for even layer l and odd layer l+1.
__device__ __forceinline__ void load_coefs(CoefBlk& b, int l, int lane) {
    const float4* ce = g_coef + (size_t)l * N_PAIR;
    const float4* co = g_coef + (size_t)(l + 1) * N_PAIR;
    #pragma unroll
    for (int k = 0; k < 8; k++) b.c[k]     = __ldg(&ce[k * 32 + lane]);
    #pragma unroll
    for (int k = 0; k < 8; k++) b.c[k + 8] = __ldg(&co[k * 32 + lane]);
    int lm = (lane > 0) ? (lane - 1) : 0;   // lane0 value unused (port 0 pass)
    float4 cx = __ldg(&co[7 * 32 + lm]);
    b.cx = make_float2(cx.x, cx.y);
}

// EVEN layer: pairs (16*lane+2k, 16*lane+2k+1), all lane-local.
__device__ __forceinline__ void do_even(float2* s, const float4* c) {
    #pragma unroll
    for (int k = 0; k < 8; k++)
        butterfly(s[2 * k], s[2 * k + 1], c[k]);
}

// ODD layer: local pairs (2k+1, 2k+2) for k=0..6; cross pair
// (16*lane+15, 16*(lane+1)) via shuffles; ports 0 and 511 pass through.
__device__ __forceinline__ void do_odd(float2* s, const float4* c, float2 cx,
                                       int lane) {
    // snapshot neighbor values BEFORE any update this layer
    float xjr = __shfl_down_sync(0xffffffffu, s[0].x, 1);   // (lane+1).port0
    float xji = __shfl_down_sync(0xffffffffu, s[0].y, 1);
    float xir = __shfl_up_sync(0xffffffffu, s[15].x, 1);    // (lane-1).port15
    float xii = __shfl_up_sync(0xffffffffu, s[15].y, 1);
    #pragma unroll
    for (int k = 0; k < 7; k++)
        butterfly(s[2 * k + 1], s[2 * k + 2], c[k]);
    if (lane < 31) {  // upper port of cross pair: gets the phase
        float ct = c[7].x, st = c[7].y, er = c[7].z, ei = c[7].w;
        float ur = ct * s[15].x + st * xjr;
        float ui = ct * s[15].y + st * xji;
        s[15].x = er * ur - ei * ui;
        s[15].y = er * ui + ei * ur;
    }
    if (lane > 0) {   // lower port of cross pair: real coefficients
        float2 x0 = s[0];
        s[0].x = cx.x * x0.x - cx.y * xir;
        s[0].y = cx.x * x0.y - cx.y * xii;
    }
}

__global__ __launch_bounds__(32, 1)
void pm_mesh_kernel(const float* __restrict__ x, float* __restrict__ out) {
    const int lane = threadIdx.x & 31;
    const int row  = blockIdx.x;          // one warp-CTA per batch row

    float2 s[16];             // complex state: lane owns ports 16*lane..16*lane+15

    // ---- load input (real), imag = 0 ----
    const float4* x4 = reinterpret_cast<const float4*>(x);
    #pragma unroll
    for (int v = 0; v < 4; v++) {
        float4 q = x4[(size_t)row * (N_PORT / 4) + lane * 4 + v];
        s[4 * v + 0] = make_float2(q.x, 0.f);
        s[4 * v + 1] = make_float2(q.y, 0.f);
        s[4 * v + 2] = make_float2(q.z, 0.f);
        s[4 * v + 3] = make_float2(q.w, 0.f);
    }

    // ---- software-pipelined propagation: ping-pong coefficient buffers ----
    CoefBlk A, B;
    load_coefs(A, 0, lane);

    // Each outer iteration processes 4 layers (A then B) while prefetching.
    #pragma unroll 1
    for (int l = 0; l < N_LAYER; l += 4) {
        int ln1 = min(l + 2, N_LAYER - 2);   // tail clamp (result unused)
        load_coefs(B, ln1, lane);
        do_even(s, A.c);
        do_odd (s, A.c + 8, A.cx, lane);

        int ln2 = min(l + 4, N_LAYER - 2);   // tail clamp (result unused)
        load_coefs(A, ln2, lane);
        do_even(s, B.c);
        do_odd (s, B.c + 8, B.cx, lane);
    }

    // ---- square-law detection + store ----
    float4* o4 = reinterpret_cast<float4*>(out);
    #pragma unroll
    for (int v = 0; v < 4; v++) {
        float4 q;
        q.x = s[4 * v + 0].x * s[4 * v + 0].x + s[4 * v + 0].y * s[4 * v + 0].y;
        q.y = s[4 * v + 1].x * s[4 * v + 1].x + s[4 * v + 1].y * s[4 * v + 1].y;
        q.z = s[4 * v + 2].x * s[4 * v + 2].x + s[4 * v + 2].y * s[4 * v + 2].y;
        q.w = s[4 * v + 3].x * s[4 * v + 3].x + s[4 * v + 3].y * s[4 * v + 3].y;
        o4[(size_t)row * (N_PORT / 4) + lane * 4 + v] = q;
    }
}

extern "C" void kernel_launch(void* const* d_in, const int* in_sizes, int n_in,
                              void* d_out, int out_size) {
    const float* x       = (const float*)d_in[0];
    const float* thetas  = (const float*)d_in[1];
    const float* phis    = (const float*)d_in[2];
    // d_in[3] = partner (unused: structure is static)
    const int*   mzi_idx = (const int*)d_in[4];
    // d_in[5] = role (unused: structure is static)
    float* out = (float*)d_out;

    pm_coef_kernel<<<N_LAYER, N_PAIR>>>(thetas, phis, mzi_idx);
    // 1024 single-warp CTAs: spread across ALL SMs (~7 per SM on 148+ SMs)
    pm_mesh_kernel<<<1024, 32>>>(x, out);
}

// round 14
// speedup vs baseline: 1.8490x; 1.2452x over previous
#include <cuda_runtime.h>

// PhotonicMesh: 512-port Clements mesh, 512 layers, 1024 batch rows.
// R14 = R13 (best, 114.6us: 1024 single-warp CTAs, lane owns 16 ports,
// register ping-pong coef prefetch, __launch_bounds__(32,1) => 197 regs,
// no spills) with ONE change: the two divergent branches in the odd layer
// are removed (ptxas wraps each in BSSY/BSYNC, ~56cyc/divergent region):
//  - `lane < 31` guard dropped: pair 255 is identity in the table, so the
//    cross butterfly at lane31 is an exact passthrough (shfl garbage x st=0).
//  - `lane > 0` guard folded into the coefficient: cx forced to (1,0) at
//    lane 0 via SELs in load_coefs; the s[0] update becomes unconditional.

#define N_PORT  512
#define N_LAYER 512
#define N_PAIR  256
#define ATTEN_F 0.97723722095581054f   // sqrt(10^(-0.2/10))

// Coefficient table, layout: [(l*8 + k)*32 + lane] where pair p = 8*lane + k.
// Per-k load across a warp is a fully coalesced 512B read.
__device__ float4 g_coef[N_LAYER * N_PAIR];

__global__ void pm_coef_kernel(const float* __restrict__ thetas,
                               const float* __restrict__ phis,
                               const int*   __restrict__ mzi_idx) {
    int l = blockIdx.x;      // layer
    int p = threadIdx.x;     // pair index within layer
    float4 c = make_float4(1.0f, 0.0f, 1.0f, 0.0f);  // identity (unused slots)
    bool odd = (l & 1) != 0;
    bool valid = (!odd) || (p < N_PAIR - 1);         // odd layers have 255 pairs
    if (valid) {
        int i = odd ? (2 * p + 1) : (2 * p);         // upper port of the pair
        int m = mzi_idx[l * N_PORT + i];
        float st, ct, sp, cp;
        sincosf(thetas[m], &st, &ct);
        sincosf(phis[m],   &sp, &cp);
        c = make_float4(ct * ATTEN_F, st * ATTEN_F, cp, sp);
    }
    g_coef[(l * 8 + (p & 7)) * 32 + (p >> 3)] = c;
}

// new_i = e^{i phi}(ct*x_i + st*x_j) ; new_j = ct*x_j - st*x_i
__device__ __forceinline__ void butterfly(float2& xi, float2& xj, float4 c) {
    float ct = c.x, st = c.y, er = c.z, ei = c.w;
    float ur = ct * xi.x + st * xj.x;
    float ui = ct * xi.y + st * xj.y;
    float vr = ct * xj.x - st * xi.x;
    float vi = ct * xj.y - st * xi.y;
    xi.x = er * ur - ei * ui;
    xi.y = er * ui + ei * ur;
    xj.x = vr;
    xj.y = vi;
}

struct CoefBlk {
    float4 c[16];   // [0..7] even-layer pairs, [8..15] odd-layer pairs
    float2 cx;      // lane-1's odd cross-pair (ct, st); identity at lane 0
};

// Load coefficients for even layer l and odd layer l+1.
__device__ __forceinline__ void load_coefs(CoefBlk& b, int l, int lane) {
    const float4* ce = g_coef + (size_t)l * N_PAIR;
    const float4* co = g_coef + (size_t)(l + 1) * N_PAIR;
    #pragma unroll
    for (int k = 0; k < 8; k++) b.c[k]     = __ldg(&ce[k * 32 + lane]);
    #pragma unroll
    for (int k = 0; k < 8; k++) b.c[k + 8] = __ldg(&co[k * 32 + lane]);
    int lm = (lane > 0) ? (lane - 1) : 0;
    float4 cx = __ldg(&co[7 * 32 + lm]);
    // identity at lane 0 (global port 0 passthrough) — SELs, not a branch
    b.cx.x = (lane > 0) ? cx.x : 1.0f;
    b.cx.y = (lane > 0) ? cx.y : 0.0f;
}

// EVEN layer: pairs (16*lane+2k, 16*lane+2k+1), all lane-local.
__device__ __forceinline__ void do_even(float2* s, const float4* c) {
    #pragma unroll
    for (int k = 0; k < 8; k++)
        butterfly(s[2 * k], s[2 * k + 1], c[k]);
}

// ODD layer: local pairs (2k+1, 2k+2) for k=0..6; cross pair
// (16*lane+15, 16*(lane+1)) via shuffles. BRANCH-FREE:
//  - lane31: c[7] is the identity pair 255 => exact passthrough of s15
//    (undefined shfl_down value is multiplied by st = 0).
//  - lane0: cx = (1,0) => s0 unchanged (undefined shfl_up value x 0).
__device__ __forceinline__ void do_odd(float2* s, const float4* c, float2 cx) {
    // snapshot neighbor values BEFORE any update this layer
    float xjr = __shfl_down_sync(0xffffffffu, s[0].x, 1);   // (lane+1).port0
    float xji = __shfl_down_sync(0xffffffffu, s[0].y, 1);
    float xir = __shfl_up_sync(0xffffffffu, s[15].x, 1);    // (lane-1).port15
    float xii = __shfl_up_sync(0xffffffffu, s[15].y, 1);
    #pragma unroll
    for (int k = 0; k < 7; k++)
        butterfly(s[2 * k + 1], s[2 * k + 2], c[k]);
    // cross pair upper port (s15): phase applies
    {
        float ct = c[7].x, st = c[7].y, er = c[7].z, ei = c[7].w;
        float ur = ct * s[15].x + st * xjr;
        float ui = ct * s[15].y + st * xji;
        s[15].x = er * ur - ei * ui;
        s[15].y = er * ui + ei * ur;
    }
    // cross pair lower port (s0): real coefficients
    {
        float2 x0 = s[0];
        s[0].x = cx.x * x0.x - cx.y * xir;
        s[0].y = cx.x * x0.y - cx.y * xii;
    }
}

__global__ __launch_bounds__(32, 1)
void pm_mesh_kernel(const float* __restrict__ x, float* __restrict__ out) {
    const int lane = threadIdx.x & 31;
    const int row  = blockIdx.x;          // one warp-CTA per batch row

    float2 s[16];             // complex state: lane owns ports 16*lane..16*lane+15

    // ---- load input (real), imag = 0 ----
    const float4* x4 = reinterpret_cast<const float4*>(x);
    #pragma unroll
    for (int v = 0; v < 4; v++) {
        float4 q = x4[(size_t)row * (N_PORT / 4) + lane * 4 + v];
        s[4 * v + 0] = make_float2(q.x, 0.f);
        s[4 * v + 1] = make_float2(q.y, 0.f);
        s[4 * v + 2] = make_float2(q.z, 0.f);
        s[4 * v + 3] = make_float2(q.w, 0.f);
    }

    // ---- software-pipelined propagation: ping-pong coefficient buffers ----
    CoefBlk A, B;
    load_coefs(A, 0, lane);

    // Each outer iteration processes 4 layers (A then B) while prefetching.
    #pragma unroll 1
    for (int l = 0; l < N_LAYER; l += 4) {
        int ln1 = min(l + 2, N_LAYER - 2);   // tail clamp (result unused)
        load_coefs(B, ln1, lane);
        do_even(s, A.c);
        do_odd (s, A.c + 8, A.cx);

        int ln2 = min(l + 4, N_LAYER - 2);   // tail clamp (result unused)
        load_coefs(A, ln2, lane);
        do_even(s, B.c);
        do_odd (s, B.c + 8, B.cx);
    }

    // ---- square-law detection + store ----
    float4* o4 = reinterpret_cast<float4*>(out);
    #pragma unroll
    for (int v = 0; v < 4; v++) {
        float4 q;
        q.x = s[4 * v + 0].x * s[4 * v + 0].x + s[4 * v + 0].y * s[4 * v + 0].y;
        q.y = s[4 * v + 1].x * s[4 * v + 1].x + s[4 * v + 1].y * s[4 * v + 1].y;
        q.z = s[4 * v + 2].x * s[4 * v + 2].x + s[4 * v + 2].y * s[4 * v + 2].y;
        q.w = s[4 * v + 3].x * s[4 * v + 3].x + s[4 * v + 3].y * s[4 * v + 3].y;
        o4[(size_t)row * (N_PORT / 4) + lane * 4 + v] = q;
    }
}

extern "C" void kernel_launch(void* const* d_in, const int* in_sizes, int n_in,
                              void* d_out, int out_size) {
    const float* x       = (const float*)d_in[0];
    const float* thetas  = (const float*)d_in[1];
    const float* phis    = (const float*)d_in[2];
    // d_in[3] = partner (unused: structure is static)
    const int*   mzi_idx = (const int*)d_in[4];
    // d_in[5] = role (unused: structure is static)
    float* out = (float*)d_out;

    pm_coef_kernel<<<N_LAYER, N_PAIR>>>(thetas, phis, mzi_idx);
    // 1024 single-warp CTAs: spread across ALL SMs (~7 per SM on 148+ SMs)
    pm_mesh_kernel<<<1024, 32>>>(x, out);
}